// round 16
// baseline (speedup 1.0000x reference)
#include <cuda_runtime.h>
#include <cuda_fp16.h>

// RankingLoss: out = mean(1/(pred^2+eps)) + [ sum_{i:neg, j:pos} relu(pred_j - pred_i) ] / (n_neg*n_pos)
// DELTA = 0, EPS = 1e-5, B = 8192. target is int32 on the wire.
//
// R15 (11.0us) minus the compaction scan: the j-tile is staged directly as
// sentinel-masked fp16 (positives keep their value, others -> -30000 so the
// hinge is exactly 0). One __syncthreads total before the inner loop; the loop
// covers all 512 j (8 windows) -- extra arithmetic is free on this latency
// floor, the removed scan/barriers are not. Tail unchanged: 3 fixed-point
// scalar atomics + wrap ticket + one-thread finalize (graph-replay safe).

#define BLOCK   256
#define J_TILE  512
#define GXB     32               // 8192 / 256 i per block
#define GYB     16               // 8192 / 512 j per tile
#define NPART   (GXB * GYB)
#define QSCALE  1048576.0        // 2^20
#define QINV    (1.0 / 1048576.0)

__device__ unsigned long long g_pairq;   // zero-init; atomicExch self-zeros each replay
__device__ unsigned long long g_trivq;
__device__ int                g_negc;
__device__ unsigned int       g_ticket;  // wraps -> self-resets every replay

__global__ __launch_bounds__(BLOCK)
void rank_fused_kernel(const float* __restrict__ pred,
                       const int* __restrict__ target,
                       float* __restrict__ out,
                       int B) {
    __shared__ __align__(16) __half spos[J_TILE];

    const int tid = threadIdx.x;
    const int lid = tid & 31;
    const int wid = tid >> 5;
    const int bx  = blockIdx.x;
    const int by  = blockIdx.y;
    const int j0  = by * J_TILE;

    // ---- Stage j-tile (2 elements/thread) as sentinel-masked fp16 ----
    const float2 pj = reinterpret_cast<const float2*>(pred + j0)[tid];
    const int2   tj = reinterpret_cast<const int2*>(target + j0)[tid];
    // i-side loads issued early (overlap with staging)
    const int i = bx * BLOCK + tid;
    const float pif = pred[i];
    const bool is_neg = (target[i] == 0);

    {
        __half2 hv;
        hv.x = __float2half_rn((tj.x == 1) ? pj.x : -30000.0f);
        hv.y = __float2half_rn((tj.y == 1) ? pj.y : -30000.0f);
        reinterpret_cast<__half2*>(spos)[tid] = hv;
    }
    __syncthreads();

    // ---- Inner loop: 1 i per thread over all 512 sentinel-masked j ----
    const __half2 npi2 = __float2half2_rn(-pif);
    const __half2 one2 = __float2half2_rn(1.0f);
    const __half2 z2   = __float2half2_rn(0.0f);
    const uint4* sp4 = reinterpret_cast<const uint4*>(spos);

    float facc = 0.0f;
    #pragma unroll 1
    for (int q = 0; q < J_TILE / 8; q += 8) {   // 8 windows of 64 j
        __half2 A = z2, C = z2;
        #pragma unroll
        for (int r = 0; r < 8; r += 2) {
            const uint4 u = sp4[q + r];
            const uint4 v = sp4[q + r + 1];
            A = __hadd2(A, __hfma2_relu(*(const __half2*)&u.x, one2, npi2));
            A = __hadd2(A, __hfma2_relu(*(const __half2*)&u.y, one2, npi2));
            A = __hadd2(A, __hfma2_relu(*(const __half2*)&u.z, one2, npi2));
            A = __hadd2(A, __hfma2_relu(*(const __half2*)&u.w, one2, npi2));
            C = __hadd2(C, __hfma2_relu(*(const __half2*)&v.x, one2, npi2));
            C = __hadd2(C, __hfma2_relu(*(const __half2*)&v.y, one2, npi2));
            C = __hadd2(C, __hfma2_relu(*(const __half2*)&v.z, one2, npi2));
            C = __hadd2(C, __hfma2_relu(*(const __half2*)&v.w, one2, npi2));
        }
        facc += (__low2float(A) + __high2float(A)) + (__low2float(C) + __high2float(C));
    }
    if (!is_neg) facc = 0.0f;

    // ---- Block reduce pair partial (f32), tid0 emits ONE u64 atomic ----
    #pragma unroll
    for (int off = 16; off > 0; off >>= 1)
        facc += __shfl_down_sync(0xFFFFFFFFu, facc, off);
    __shared__ float wsum[BLOCK / 32];
    if (lid == 0) wsum[wid] = facc;
    __syncthreads();

    // ---- by==0 blocks: trivial term (double) + neg count ----
    if (by == 0) {
        double td = (double)(1.0f / (pif * pif + 1e-5f));
        int    nc = is_neg ? 1 : 0;
        #pragma unroll
        for (int off = 16; off > 0; off >>= 1) {
            td += __shfl_down_sync(0xFFFFFFFFu, td, off);
            nc += __shfl_down_sync(0xFFFFFFFFu, nc, off);
        }
        __shared__ double twsum[BLOCK / 32];
        __shared__ int    nwsum[BLOCK / 32];
        if (lid == 0) { twsum[wid] = td; nwsum[wid] = nc; }
        __syncthreads();
        if (tid == 0) {
            double tt = 0.0; int nn = 0;
            #pragma unroll
            for (int w = 0; w < BLOCK / 32; ++w) { tt += twsum[w]; nn += nwsum[w]; }
            atomicAdd(&g_trivq, (unsigned long long)(long long)llrint(tt * QSCALE));
            atomicAdd(&g_negc, nn);
        }
    }

    // tid0: pair atomic -> fence -> ticket
    __shared__ bool s_last;
    if (tid == 0) {
        float bp = 0.0f;
        #pragma unroll
        for (int w = 0; w < BLOCK / 32; ++w) bp += wsum[w];
        atomicAdd(&g_pairq, (unsigned long long)(long long)llrint((double)bp * QSCALE));
        __threadfence();
        const unsigned int old = atomicInc(&g_ticket, (unsigned int)NPART - 1u);
        s_last = (old == (unsigned int)NPART - 1u);
    }
    __syncthreads();
    if (!s_last) return;

    // ---- Minimal tail: read + self-zero 3 scalars, compute, store ----
    if (tid == 0) {
        __threadfence();   // acquire: order scalar reads after all ticket arrivals
        const unsigned long long pq = atomicExch(&g_pairq, 0ull);
        const unsigned long long tq = atomicExch(&g_trivq, 0ull);
        const int                ng = atomicExch(&g_negc, 0);
        const double pair = (double)(long long)pq * QINV;
        const double triv = (double)(long long)tq * QINV;
        const double n_neg = (double)ng;
        const double n_pos = (double)B - n_neg;
        const double N = n_neg * n_pos;
        out[0] = (float)(triv / (double)B + pair / N);
    }
}

extern "C" void kernel_launch(void* const* d_in, const int* in_sizes, int n_in,
                              void* d_out, int out_size) {
    const float* pred   = (const float*)d_in[0];
    const int*   target = (const int*)d_in[1];
    float*       out    = (float*)d_out;
    const int B = in_sizes[0];   // 8192

    dim3 grid(GXB, GYB);         // 512 blocks
    rank_fused_kernel<<<grid, BLOCK>>>(pred, target, out, B);
}